// round 4
// baseline (speedup 1.0000x reference)
#include <cuda_runtime.h>
#include <cstdint>

// Problem constants
#define SEQ       32768
#define NT        512
#define START_TAG 510
#define END_TAG   511
#define NEG_FILL  (-10000.0f)

// Geometry: 128 CTAs x 128 threads; CTA c owns tags 4c..4c+3 (1 tag per warp);
// lane owns source range [16*lane, 16*lane+16). Warps are fully independent.
#define GRIDN 128
#define TPB   128
#define IPL   16

// Traceback segmentation
#define SEGS   128
#define SEGLEN 256   // SEGS * SEGLEN == SEQ

// ---------------------------------------------------------------------------
// Device scratch
// ---------------------------------------------------------------------------
// Packed {epoch:u32 (hi), value:f32 bits (lo)} per tag, double-buffered by
// epoch parity. A single 64-bit store is the publish AND the flag.
__device__ __align__(128) unsigned long long g_pair[2][NT];
__device__ unsigned short g_bp[SEQ][NT];     // backpointers (32 MB)
__device__ int            g_best;            // terminal argmax tag
__device__ unsigned short g_exit[SEGS][NT];  // per-segment exit map

// Order-preserving float<->uint bijection (exact, monotone)
__device__ __forceinline__ unsigned enc32(float f) {
    unsigned u = __float_as_uint(f);
    return (u & 0x80000000u) ? ~u : (u | 0x80000000u);
}
__device__ __forceinline__ float dec32(unsigned o) {
    unsigned u = (o & 0x80000000u) ? (o & 0x7fffffffu) : ~o;
    return __uint_as_float(u);
}

// L2-direct 16B volatile load (2 pairs)
__device__ __forceinline__ uint4 ldvol4(const uint4* p) {
    uint4 r;
    asm volatile("ld.volatile.global.v4.u32 {%0,%1,%2,%3}, [%4];"
                 : "=r"(r.x), "=r"(r.y), "=r"(r.z), "=r"(r.w)
                 : "l"(p) : "memory");
    return r;
}
// Atomic 64-bit publish of {epoch, value}
__device__ __forceinline__ void stpair(unsigned long long* p, unsigned ep, float v) {
    unsigned long long d =
        ((unsigned long long)ep << 32) | (unsigned long long)__float_as_uint(v);
    asm volatile("st.relaxed.gpu.global.u64 [%0], %1;" :: "l"(p), "l"(d) : "memory");
}
__device__ __forceinline__ unsigned long long ldpair(const unsigned long long* p) {
    unsigned long long d;
    asm volatile("ld.volatile.global.u64 %0, [%1];" : "=l"(d) : "l"(p) : "memory");
    return d;
}

// Poll this lane's 16 pairs of epoch `ep` (buffer ep&1); retries reload only
// the stale 16B vectors.
__device__ __forceinline__ void poll_alphas(float* a, unsigned ep, int ibase) {
    const uint4* base = reinterpret_cast<const uint4*>(&g_pair[ep & 1][ibase]);
    unsigned pend = 0xffu;
    do {
#pragma unroll
        for (int v = 0; v < 8; ++v) {
            if (pend & (1u << v)) {
                uint4 p = ldvol4(base + v);
                if (p.y == ep && p.w == ep) {
                    a[2 * v]     = __uint_as_float(p.x);
                    a[2 * v + 1] = __uint_as_float(p.z);
                    pend &= ~(1u << v);
                }
            }
        }
    } while (pend);
}

// Poison epochs so previous-replay values never look fresh.
__global__ void viterbi_reset() {
    const int i = threadIdx.x;            // 512 threads
    g_pair[0][i] = 0xFFFFFFFF00000000ull;
    g_pair[1][i] = 0xFFFFFFFF00000000ull;
}

// ---------------------------------------------------------------------------
// Main kernel: 512 free-running warps, barrier-free seqlock exchange
// ---------------------------------------------------------------------------
__global__ void __launch_bounds__(TPB, 1) viterbi_main(
    const float* __restrict__ unary,   // [SEQ][NT]
    const float* __restrict__ trans,   // [NT][NT]  (tr[j][i])
    float* __restrict__ out, int out_size)
{
    const int tid   = threadIdx.x;
    const int warp  = tid >> 5;
    const int lane  = tid & 31;
    const int cta   = blockIdx.x;
    const int j     = (cta << 2) + warp;   // tag owned by this warp
    const int ibase = lane << 4;           // first source tag for this lane

    // Register-resident transition slice tr[j][ibase+k]
    float tr[IPL];
    {
        const float4* tp = reinterpret_cast<const float4*>(trans + j * NT + ibase);
#pragma unroll
        for (int q = 0; q < 4; ++q) {
            float4 v = __ldg(tp + q);
            tr[4*q+0] = v.x; tr[4*q+1] = v.y; tr[4*q+2] = v.z; tr[4*q+3] = v.w;
        }
    }

    // Publish initial alphas as epoch 0 (buffer 0)
    if (lane == 0)
        stpair(&g_pair[0][j], 0u, (j == START_TAG) ? 0.0f : NEG_FILL);

    float ucur = 0.0f, unext = 0.0f;
    if (lane == 0) ucur = __ldg(unary + j);   // u[0][j]

    // Acquire epoch-0 alphas
    float a[IPL];
    poll_alphas(a, 0u, ibase);

#pragma unroll 1
    for (int t = 0; t < SEQ; ++t) {
        // Prefetch next unary (consumed next iteration)
        if (lane == 0) {
            const int tn = (t + 1 < SEQ) ? (t + 1) : (SEQ - 1);
            unext = __ldg(unary + tn * NT + j);
        }

        // scores: s_i = alpha_i + tr[j][i]   (bit-identical to reference)
        float s[IPL];
#pragma unroll
        for (int k = 0; k < IPL; ++k) s[k] = a[k] + tr[k];

        float m0 = fmaxf(fmaxf(s[0],  s[1]),  fmaxf(s[2],  s[3]));
        float m1 = fmaxf(fmaxf(s[4],  s[5]),  fmaxf(s[6],  s[7]));
        float m2 = fmaxf(fmaxf(s[8],  s[9]),  fmaxf(s[10], s[11]));
        float m3 = fmaxf(fmaxf(s[12], s[13]), fmaxf(s[14], s[15]));
        float m  = fmaxf(fmaxf(m0, m1), fmaxf(m2, m3));
        unsigned om = __reduce_max_sync(0xffffffffu, enc32(m));
        float vit = dec32(om);

        // Publish new alpha immediately: {epoch t+1, vit + u_t[j]}
        if (lane == 0)
            stpair(&g_pair[(t + 1) & 1][j], (unsigned)(t + 1), vit + ucur);
        ucur = unext;

        // --- publish shadow: backpointer (exact equality, first index) ---
        unsigned mask = 0u;
#pragma unroll
        for (int k = 0; k < IPL; ++k) if (s[k] == vit) mask |= (1u << k);
        const unsigned bal = __ballot_sync(0xffffffffu, mask != 0u);
        const int leader = __ffs(bal) - 1;
        if (lane == leader)
            g_bp[t][j] = (unsigned short)(ibase + __ffs(mask) - 1);
        // -----------------------------------------------------------------

        // Acquire epoch t+1 alphas (the poll IS the data load)
        if (t + 1 < SEQ) poll_alphas(a, (unsigned)(t + 1), ibase);
    }

    // Terminal reduce on CTA 0: needs all tags at epoch SEQ (buffer 0)
    if (cta == 0) {
        __shared__ unsigned long long sh[TPB];
        unsigned long long best = 0ull;
#pragma unroll
        for (int q = 0; q < 4; ++q) {
            const int i = tid * 4 + q;
            unsigned long long pv;
            do { pv = ldpair(&g_pair[0][i]); } while ((unsigned)(pv >> 32) != (unsigned)SEQ);
            float term = __uint_as_float((unsigned)pv) + __ldg(trans + END_TAG * NT + i);
            // larger value wins; exact tie -> smaller index (first-max)
            unsigned long long key =
                ((unsigned long long)enc32(term) << 32) | (unsigned)(NT - 1 - i);
            if (key > best) best = key;
        }
        sh[tid] = best;
        __syncthreads();
        if (tid == 0) {
            unsigned long long b = sh[0];
            for (int k = 1; k < TPB; ++k) if (sh[k] > b) b = sh[k];
            g_best = NT - 1 - (int)(b & 0xffffffffu);
            const float sc = dec32((unsigned)(b >> 32));
            if (out_size > SEQ) out[SEQ] = sc;   // (path, score) layout
        }
    }
}

// ---------------------------------------------------------------------------
// Traceback pass A: per-segment exit map for every possible entry tag.
// ---------------------------------------------------------------------------
__global__ void viterbi_exits() {
    const int s = blockIdx.x;
    int cur = threadIdx.x;              // candidate entry tag
    const int tbase = s * SEGLEN;
    for (int t = tbase + SEGLEN - 1; t >= tbase; --t)
        cur = g_bp[t][cur];
    g_exit[s][threadIdx.x] = (unsigned short)cur;
}

// ---------------------------------------------------------------------------
// Traceback pass B (sequential compose) + C (parallel path write)
// ---------------------------------------------------------------------------
__global__ void viterbi_trace(float* __restrict__ out, int out_size) {
    __shared__ int entry[SEGS];
    const int tid = threadIdx.x;
    if (tid == 0) {
        int cur = g_best;               // path[SEQ-1]
        for (int s = SEGS - 1; s >= 0; --s) {
            entry[s] = cur;
            cur = g_exit[s][cur];
        }
    }
    __syncthreads();
    int cur = entry[tid];
    const int tbase = tid * SEGLEN;
    for (int t = tbase + SEGLEN - 1; t >= tbase; --t) {
        if (t < out_size) out[t] = (float)cur;
        cur = g_bp[t][cur];
    }
}

// ---------------------------------------------------------------------------
// Launch
// ---------------------------------------------------------------------------
extern "C" void kernel_launch(void* const* d_in, const int* in_sizes, int n_in,
                              void* d_out, int out_size) {
    const float* unary = (const float*)d_in[0];   // [SEQ,1,NT] f32
    const float* trans = (const float*)d_in[1];   // [1,NT,NT]  f32
    (void)in_sizes; (void)n_in;                   // lengths == SEQ, unused
    float* out = (float*)d_out;

    viterbi_reset<<<1, NT>>>();                   // poison epochs
    viterbi_main <<<GRIDN, TPB>>>(unary, trans, out, out_size);
    viterbi_exits<<<SEGS, NT>>>();
    viterbi_trace<<<1, SEGS>>>(out, out_size);
}

// round 5
// speedup vs baseline: 2.7274x; 2.7274x over previous
#include <cuda_runtime.h>
#include <cstdint>

// Problem constants
#define SEQ       32768
#define NT        512
#define START_TAG 510
#define END_TAG   511
#define NEG_FILL  (-10000.0f)

// Geometry: 32 CTAs x 8 warps; warp owns 2 tags (j0, j0+1); lane owns
// source range [16*lane, 16*lane+16). 256 warps total = 512 tags.
#define GRIDN  32
#define WPC    8
#define TPB    (WPC * 32)
#define NWARPS (GRIDN * WPC)     // 256
#define IPL    16

// Traceback segmentation
#define SEGS   128
#define SEGLEN 256               // SEGS * SEGLEN == SEQ

// ---------------------------------------------------------------------------
// Device scratch
// ---------------------------------------------------------------------------
__device__ __align__(128) float g_alpha[2][NT];   // parity double buffer
__device__ __align__(128) int   g_wflag[NWARPS];  // per-warp publish epoch
__device__ unsigned short g_bp[SEQ][NT];          // backpointers (32 MB)
__device__ int            g_best;                 // terminal argmax tag
__device__ unsigned short g_exit[SEGS][NT];       // per-segment exit map

// Order-preserving float<->uint bijection (exact, monotone)
__device__ __forceinline__ unsigned enc32(float f) {
    unsigned u = __float_as_uint(f);
    return (u & 0x80000000u) ? ~u : (u | 0x80000000u);
}
__device__ __forceinline__ float dec32(unsigned o) {
    unsigned u = (o & 0x80000000u) ? (o & 0x7fffffffu) : ~o;
    return __uint_as_float(u);
}

__device__ __forceinline__ uint4 ldvol4(const uint4* p) {
    uint4 r;
    asm volatile("ld.volatile.global.v4.u32 {%0,%1,%2,%3}, [%4];"
                 : "=r"(r.x), "=r"(r.y), "=r"(r.z), "=r"(r.w)
                 : "l"(p) : "memory");
    return r;
}
__device__ __forceinline__ void st_alpha2(float* p, float lo, float hi) {
    unsigned long long d = ((unsigned long long)__float_as_uint(hi) << 32)
                         | (unsigned long long)__float_as_uint(lo);
    asm volatile("st.relaxed.gpu.global.u64 [%0], %1;" :: "l"(p), "l"(d) : "memory");
}
__device__ __forceinline__ void st_flag_rel(int* p, int v) {
    asm volatile("st.release.gpu.global.s32 [%0], %1;" :: "l"(p), "r"(v) : "memory");
}

// Poller (warp 0 of each CTA): wait until every warp's flag >= target.
// 256 flags, lane covers flags [8*lane, 8*lane+8) via two 16B vector loads.
__device__ __forceinline__ void poll_flags(int lane, int target) {
    const uint4* p = reinterpret_cast<const uint4*>(g_wflag) + (lane << 1);
    for (;;) {
        uint4 f0 = ldvol4(p);
        uint4 f1 = ldvol4(p + 1);
        int m0 = min(min((int)f0.x, (int)f0.y), min((int)f0.z, (int)f0.w));
        int m1 = min(min((int)f1.x, (int)f1.y), min((int)f1.z, (int)f1.w));
        if (__all_sync(0xffffffffu, min(m0, m1) >= target)) break;
    }
    asm volatile("fence.acq_rel.gpu;" ::: "memory");
}

// Reset flags each launch so previous-replay epochs never look fresh.
__global__ void viterbi_reset() { g_wflag[threadIdx.x] = -1; }

// ---------------------------------------------------------------------------
// Main kernel: per-warp release flags, one bar.sync/step, parity buffers
// ---------------------------------------------------------------------------
__global__ void __launch_bounds__(TPB, 1) viterbi_main(
    const float* __restrict__ unary,   // [SEQ][NT]
    const float* __restrict__ trans,   // [NT][NT]  (tr[j][i])
    float* __restrict__ out, int out_size)
{
    const int tid   = threadIdx.x;
    const int warp  = tid >> 5;
    const int lane  = tid & 31;
    const int cta   = blockIdx.x;
    const int widx  = cta * WPC + warp;
    const int j0    = widx << 1;           // tags j0, j0+1
    const int ibase = lane << 4;

    // Register-resident transition slices for both tags
    float trA[IPL], trB[IPL];
    {
        const float4* ta = reinterpret_cast<const float4*>(trans + j0 * NT + ibase);
        const float4* tb = reinterpret_cast<const float4*>(trans + (j0 + 1) * NT + ibase);
#pragma unroll
        for (int q = 0; q < 4; ++q) {
            float4 v = __ldg(ta + q);
            trA[4*q+0]=v.x; trA[4*q+1]=v.y; trA[4*q+2]=v.z; trA[4*q+3]=v.w;
            float4 w = __ldg(tb + q);
            trB[4*q+0]=w.x; trB[4*q+1]=w.y; trB[4*q+2]=w.z; trB[4*q+3]=w.w;
        }
    }

    // Publish epoch-0 alphas + flag (same thread: release orders them)
    if (lane == 0) {
        float a0 = (j0     == START_TAG) ? 0.0f : NEG_FILL;
        float a1 = (j0 + 1 == START_TAG) ? 0.0f : NEG_FILL;
        st_alpha2(&g_alpha[0][j0], a0, a1);
        st_flag_rel(&g_wflag[widx], 0);
    }
    float u0 = __ldg(unary + j0);          // u[0][j0]   (uniform broadcast)
    float u1 = __ldg(unary + j0 + 1);

    // Acquire epoch 0
    if (warp == 0) poll_flags(lane, 0);
    __syncthreads();

    float a[IPL];
    {
        const float4* ap = reinterpret_cast<const float4*>(&g_alpha[0][ibase]);
#pragma unroll
        for (int q = 0; q < 4; ++q) {
            float4 v = __ldcg(ap + q);
            a[4*q+0]=v.x; a[4*q+1]=v.y; a[4*q+2]=v.z; a[4*q+3]=v.w;
        }
    }

#pragma unroll 1
    for (int t = 0; t < SEQ; ++t) {
        // Prefetch next unary
        const int tn = (t + 1 < SEQ) ? (t + 1) : (SEQ - 1);
        const float nu0 = __ldg(unary + tn * NT + j0);
        const float nu1 = __ldg(unary + tn * NT + j0 + 1);

        // scores for both tags (bit-identical to reference)
        float sA[IPL], sB[IPL];
#pragma unroll
        for (int k = 0; k < IPL; ++k) { sA[k] = a[k] + trA[k]; sB[k] = a[k] + trB[k]; }

        float mA = fmaxf(
            fmaxf(fmaxf(fmaxf(sA[0],sA[1]),fmaxf(sA[2],sA[3])),
                  fmaxf(fmaxf(sA[4],sA[5]),fmaxf(sA[6],sA[7]))),
            fmaxf(fmaxf(fmaxf(sA[8],sA[9]),fmaxf(sA[10],sA[11])),
                  fmaxf(fmaxf(sA[12],sA[13]),fmaxf(sA[14],sA[15]))));
        float mB = fmaxf(
            fmaxf(fmaxf(fmaxf(sB[0],sB[1]),fmaxf(sB[2],sB[3])),
                  fmaxf(fmaxf(sB[4],sB[5]),fmaxf(sB[6],sB[7]))),
            fmaxf(fmaxf(fmaxf(sB[8],sB[9]),fmaxf(sB[10],sB[11])),
                  fmaxf(fmaxf(sB[12],sB[13]),fmaxf(sB[14],sB[15]))));
        const float vitA = dec32(__reduce_max_sync(0xffffffffu, enc32(mA)));
        const float vitB = dec32(__reduce_max_sync(0xffffffffu, enc32(mB)));

        // Publish epoch t+1: alphas then per-warp flag (same-thread release)
        if (lane == 0) {
            st_alpha2(&g_alpha[(t + 1) & 1][j0], vitA + u0, vitB + u1);
            st_flag_rel(&g_wflag[widx], t + 1);
        }
        u0 = nu0; u1 = nu1;

        // --- publish shadow: backpointers (exact equality, first index) ---
        unsigned kA = 0u, kB = 0u;
#pragma unroll
        for (int k = 0; k < IPL; ++k) {
            if (sA[k] == vitA) kA |= (1u << k);
            if (sB[k] == vitB) kB |= (1u << k);
        }
        const unsigned balA = __ballot_sync(0xffffffffu, kA != 0u);
        if (lane == __ffs(balA) - 1)
            g_bp[t][j0] = (unsigned short)(ibase + __ffs(kA) - 1);
        const unsigned balB = __ballot_sync(0xffffffffu, kB != 0u);
        if (lane == __ffs(balB) - 1)
            g_bp[t][j0 + 1] = (unsigned short)(ibase + __ffs(kB) - 1);
        // ------------------------------------------------------------------

        // Acquire epoch t+1 (poller warp + CTA barrier), then reload alphas
        if (warp == 0) poll_flags(lane, t + 1);
        __syncthreads();
        {
            const float4* ap =
                reinterpret_cast<const float4*>(&g_alpha[(t + 1) & 1][ibase]);
#pragma unroll
            for (int q = 0; q < 4; ++q) {
                float4 v = __ldcg(ap + q);
                a[4*q+0]=v.x; a[4*q+1]=v.y; a[4*q+2]=v.z; a[4*q+3]=v.w;
            }
        }
    }

    // Terminal reduce: CTA 0 warp 0 holds the full epoch-SEQ alpha vector
    // (buffer 0, since SEQ is even) in a[] across its 32 lanes.
    if (cta == 0 && warp == 0) {
        float te[IPL];
        {
            const float4* tp =
                reinterpret_cast<const float4*>(trans + END_TAG * NT + ibase);
#pragma unroll
            for (int q = 0; q < 4; ++q) {
                float4 v = __ldg(tp + q);
                te[4*q+0]=v.x; te[4*q+1]=v.y; te[4*q+2]=v.z; te[4*q+3]=v.w;
            }
        }
        float best = -3.4e38f; int bidx = 0;
#pragma unroll
        for (int k = 0; k < IPL; ++k) {
            const float term = a[k] + te[k];
            if (term > best) { best = term; bidx = ibase + k; }  // keeps first
        }
        const float vit = dec32(__reduce_max_sync(0xffffffffu, enc32(best)));
        const unsigned bal = __ballot_sync(0xffffffffu, best == vit);
        if (lane == __ffs(bal) - 1) {
            g_best = bidx;
            if (out_size > SEQ) out[SEQ] = vit;   // (path, score) layout
        }
    }
}

// ---------------------------------------------------------------------------
// Traceback pass A: per-segment exit map for every possible entry tag.
// ---------------------------------------------------------------------------
__global__ void viterbi_exits() {
    const int s = blockIdx.x;
    int cur = threadIdx.x;
    const int tbase = s * SEGLEN;
    for (int t = tbase + SEGLEN - 1; t >= tbase; --t)
        cur = g_bp[t][cur];
    g_exit[s][threadIdx.x] = (unsigned short)cur;
}

// ---------------------------------------------------------------------------
// Traceback pass B (sequential compose) + C (parallel path write)
// ---------------------------------------------------------------------------
__global__ void viterbi_trace(float* __restrict__ out, int out_size) {
    __shared__ int entry[SEGS];
    const int tid = threadIdx.x;
    if (tid == 0) {
        int cur = g_best;
        for (int s = SEGS - 1; s >= 0; --s) {
            entry[s] = cur;
            cur = g_exit[s][cur];
        }
    }
    __syncthreads();
    int cur = entry[tid];
    const int tbase = tid * SEGLEN;
    for (int t = tbase + SEGLEN - 1; t >= tbase; --t) {
        if (t < out_size) out[t] = (float)cur;
        cur = g_bp[t][cur];
    }
}

// ---------------------------------------------------------------------------
// Launch
// ---------------------------------------------------------------------------
extern "C" void kernel_launch(void* const* d_in, const int* in_sizes, int n_in,
                              void* d_out, int out_size) {
    const float* unary = (const float*)d_in[0];   // [SEQ,1,NT] f32
    const float* trans = (const float*)d_in[1];   // [1,NT,NT]  f32
    (void)in_sizes; (void)n_in;                   // lengths == SEQ, unused
    float* out = (float*)d_out;

    viterbi_reset<<<1, NWARPS>>>();
    viterbi_main <<<GRIDN, TPB>>>(unary, trans, out, out_size);
    viterbi_exits<<<SEGS, NT>>>();
    viterbi_trace<<<1, SEGS>>>(out, out_size);
}

// round 6
// speedup vs baseline: 5.9936x; 2.1976x over previous
#include <cuda_runtime.h>
#include <cstdint>

// Problem constants
#define SEQ       32768
#define NT        512
#define START_TAG 510
#define END_TAG   511
#define NEG_FILL  (-10000.0f)

// Forward geometry: one 8-CTA cluster x 512 threads (16 warps).
// Warp widx owns 4 tags j0=4*widx.. ; lane owns sources [16*lane,16*lane+16).
#define CLN      8
#define FW_TPB   512
#define WPC_FW   16
#define NWARP_FW (CLN * WPC_FW)   // 128 producer warps
#define TPW      4

// Backpointer-recompute geometry
#define BP_JGRP  8                 // tags per CTA (1 per warp, 256 threads)
#define BP_TCH   2048              // time chunk
#define BP_GRIDX (NT / BP_JGRP)    // 64
#define BP_GRIDY (SEQ / BP_TCH)    // 16

// Traceback segmentation
#define SEGS   128
#define SEGLEN 256                 // SEGS * SEGLEN == SEQ

// ---------------------------------------------------------------------------
// Device scratch (static: allocation-free)
// ---------------------------------------------------------------------------
__device__ __align__(128) float          g_hist[SEQ + 1][NT];   // alpha history (~64MB)
__device__ __align__(128) unsigned short g_bp[SEQ][NT];         // backpointers (32MB)
__device__ int            g_best;                               // terminal argmax tag
__device__ unsigned short g_exit[SEGS][NT];                     // per-segment exit map

// Order-preserving float<->uint bijection (exact, monotone)
__device__ __forceinline__ unsigned enc32(float f) {
    unsigned u = __float_as_uint(f);
    return (u & 0x80000000u) ? ~u : (u | 0x80000000u);
}
__device__ __forceinline__ float dec32(unsigned o) {
    unsigned u = (o & 0x80000000u) ? (o & 0x7fffffffu) : ~o;
    return __uint_as_float(u);
}

__device__ __forceinline__ uint32_t smem_u32(const void* p) {
    uint32_t a;
    asm("{ .reg .u64 t; cvta.to.shared.u64 t, %1; cvt.u32.u64 %0, t; }"
        : "=r"(a) : "l"(p));
    return a;
}
__device__ __forceinline__ uint32_t mapa_u32(uint32_t local, uint32_t rank) {
    uint32_t r;
    asm("mapa.shared::cluster.u32 %0, %1, %2;" : "=r"(r) : "r"(local), "r"(rank));
    return r;
}
// Weak DSMEM store of two packed floats (8B atomic unit)
__device__ __forceinline__ void st_dsm2(uint32_t addr, float x, float y) {
    unsigned long long d = ((unsigned long long)__float_as_uint(y) << 32)
                         | (unsigned long long)__float_as_uint(x);
    asm volatile("st.shared::cluster.u64 [%0], %1;" :: "r"(addr), "l"(d) : "memory");
}
// Release DSMEM flag store: orders this thread's prior cluster stores
__device__ __forceinline__ void st_flag_rel(uint32_t addr, unsigned v) {
    asm volatile("st.release.cluster.shared::cluster.u32 [%0], %1;"
                 :: "r"(addr), "r"(v) : "memory");
}
// Poll 128 local-SMEM flags (4/lane) until min >= target. Uniform exit.
__device__ __forceinline__ void poll_flags(uint32_t pollA, unsigned target) {
    for (;;) {
        unsigned x, y, z, w;
        asm volatile("ld.volatile.shared.v4.u32 {%0,%1,%2,%3}, [%4];"
                     : "=r"(x), "=r"(y), "=r"(z), "=r"(w) : "r"(pollA) : "memory");
        unsigned m = min(min(x, y), min(z, w));
        if (__reduce_min_sync(0xffffffffu, m) >= target) break;
    }
}

// ---------------------------------------------------------------------------
// Forward pass: 8-CTA cluster, DSMEM alpha broadcast, local-SMEM flag poll.
// Values only (no backpointers); streams alpha history to g_hist.
// ---------------------------------------------------------------------------
__global__ void __launch_bounds__(FW_TPB, 1) __cluster_dims__(CLN, 1, 1)
viterbi_fwd(const float* __restrict__ unary,   // [SEQ][NT]
            const float* __restrict__ trans,   // [NT][NT]  tr[j][i]
            float* __restrict__ out, int out_size)
{
    __shared__ float    s_alpha[2][NT];     // parity double buffer (full vector)
    __shared__ unsigned s_flag[NWARP_FW];   // per-producer-warp epoch flags

    const int tid   = threadIdx.x;
    const int warp  = tid >> 5;
    const int lane  = tid & 31;
    const int cta   = blockIdx.x;           // == cluster rank (grid = 1 cluster)
    const int widx  = cta * WPC_FW + warp;
    const int j0    = widx * TPW;
    const int ibase = lane << 4;

    // Init local SMEM, then cluster barrier so no remote store can land
    // before its target CTA finished initializing.
    for (int i = tid; i < NT; i += FW_TPB) { s_alpha[0][i] = 0.f; s_alpha[1][i] = 0.f; }
    if (tid < NWARP_FW) s_flag[tid] = 0u;
    __syncthreads();
    asm volatile("barrier.cluster.arrive.aligned;" ::: "memory");
    asm volatile("barrier.cluster.wait.aligned;"   ::: "memory");

    // Register-resident transition slices for the 4 owned tags
    float tr0[16], tr1[16], tr2[16], tr3[16];
#pragma unroll
    for (int q = 0; q < 4; ++q) {
        float4 v0 = __ldg((const float4*)(trans + (j0 + 0) * NT + ibase) + q);
        float4 v1 = __ldg((const float4*)(trans + (j0 + 1) * NT + ibase) + q);
        float4 v2 = __ldg((const float4*)(trans + (j0 + 2) * NT + ibase) + q);
        float4 v3 = __ldg((const float4*)(trans + (j0 + 3) * NT + ibase) + q);
        tr0[4*q]=v0.x; tr0[4*q+1]=v0.y; tr0[4*q+2]=v0.z; tr0[4*q+3]=v0.w;
        tr1[4*q]=v1.x; tr1[4*q+1]=v1.y; tr1[4*q+2]=v1.z; tr1[4*q+3]=v1.w;
        tr2[4*q]=v2.x; tr2[4*q+1]=v2.y; tr2[4*q+2]=v2.z; tr2[4*q+3]=v2.w;
        tr3[4*q]=v3.x; tr3[4*q+1]=v3.y; tr3[4*q+2]=v3.z; tr3[4*q+3]=v3.w;
    }

    // Remote addresses: lane k (<8) targets cluster CTA k at identical offsets
    uint32_t ra0 = 0, ra1 = 0, rf = 0;
    {
        const uint32_t l0 = smem_u32(&s_alpha[0][j0]);
        const uint32_t l1 = smem_u32(&s_alpha[1][j0]);
        const uint32_t lf = smem_u32(&s_flag[widx]);
        if (lane < CLN) {
            ra0 = mapa_u32(l0, (uint32_t)lane);
            ra1 = mapa_u32(l1, (uint32_t)lane);
            rf  = mapa_u32(lf, (uint32_t)lane);
        }
    }
    const uint32_t pollA = smem_u32(&s_flag[lane * 4]);

    // Publish epoch 0 (flag value = epoch+1 = 1; init 0 never matches)
    {
        float n0 = (j0 + 0 == START_TAG) ? 0.f : NEG_FILL;
        float n1 = (j0 + 1 == START_TAG) ? 0.f : NEG_FILL;
        float n2 = (j0 + 2 == START_TAG) ? 0.f : NEG_FILL;
        float n3 = (j0 + 3 == START_TAG) ? 0.f : NEG_FILL;
        if (lane < CLN) {
            st_dsm2(ra0,     n0, n1);
            st_dsm2(ra0 + 8, n2, n3);
            st_flag_rel(rf, 1u);
        }
        if (lane == 0) {
            float4 h; h.x = n0; h.y = n1; h.z = n2; h.w = n3;
            *(float4*)&g_hist[0][j0] = h;
        }
    }

    float4 u = __ldg((const float4*)(unary + j0));   // u[0][j0..j0+3]

#pragma unroll 1
    for (int t = 0; t < SEQ; ++t) {
        // Acquire epoch t: all 128 producer flags >= t+1 (local SMEM spin)
        poll_flags(pollA, (unsigned)(t + 1));

        // Prefetch next unary row early (latency overlaps the math below)
        const int tn = (t + 1 < SEQ) ? (t + 1) : (SEQ - 1);
        const float4 un = __ldg((const float4*)(unary + tn * NT + j0));

        // Load this lane's 16 alphas from local SMEM (parity t&1)
        const float* ab = &s_alpha[t & 1][ibase];
        float a[16];
#pragma unroll
        for (int q = 0; q < 4; ++q) {
            float4 v = *(const float4*)(ab + q * 4);
            a[4*q]=v.x; a[4*q+1]=v.y; a[4*q+2]=v.z; a[4*q+3]=v.w;
        }

        // Max-plus: m_r = max_k (a[k] + tr_r[k])   (bit-identical fp32 ops)
        float m0 = a[0]+tr0[0], m1 = a[0]+tr1[0], m2 = a[0]+tr2[0], m3 = a[0]+tr3[0];
#pragma unroll
        for (int k = 1; k < 16; ++k) {
            m0 = fmaxf(m0, a[k] + tr0[k]);
            m1 = fmaxf(m1, a[k] + tr1[k]);
            m2 = fmaxf(m2, a[k] + tr2[k]);
            m3 = fmaxf(m3, a[k] + tr3[k]);
        }
        const float v0 = dec32(__reduce_max_sync(0xffffffffu, enc32(m0)));
        const float v1 = dec32(__reduce_max_sync(0xffffffffu, enc32(m1)));
        const float v2 = dec32(__reduce_max_sync(0xffffffffu, enc32(m2)));
        const float v3 = dec32(__reduce_max_sync(0xffffffffu, enc32(m3)));

        const float w0 = v0 + u.x, w1 = v1 + u.y, w2 = v2 + u.z, w3 = v3 + u.w;

        // Publish epoch t+1: values to all 8 CTAs, then release-flag
        if (lane < CLN) {
            const uint32_t dst = ((t + 1) & 1) ? ra1 : ra0;
            st_dsm2(dst,     w0, w1);
            st_dsm2(dst + 8, w2, w3);
            st_flag_rel(rf, (unsigned)(t + 2));
        }
        // Stream alpha history (one STG.128 per warp, off critical path)
        if (lane == 8) {
            float4 h; h.x = w0; h.y = w1; h.z = w2; h.w = w3;
            *(float4*)&g_hist[t + 1][j0] = h;
        }
        u = un;
    }

    // Terminal argmax on CTA 0 warp 0: needs epoch SEQ (parity 0)
    if (cta == 0 && warp == 0) {
        poll_flags(pollA, (unsigned)(SEQ + 1));
        float s[16];
        float m = -3.402823466e38f;
#pragma unroll
        for (int q = 0; q < 4; ++q) {
            float4 tv = __ldg((const float4*)(trans + END_TAG * NT + ibase) + q);
            float4 av = *(const float4*)(&s_alpha[0][ibase] + q * 4);
            s[4*q]   = av.x + tv.x; s[4*q+1] = av.y + tv.y;
            s[4*q+2] = av.z + tv.z; s[4*q+3] = av.w + tv.w;
        }
#pragma unroll
        for (int k = 0; k < 16; ++k) m = fmaxf(m, s[k]);
        const float vit = dec32(__reduce_max_sync(0xffffffffu, enc32(m)));
        int idx = 0;
#pragma unroll
        for (int k = 15; k >= 0; --k) if (s[k] == vit) idx = k;   // first index
        const unsigned bal = __ballot_sync(0xffffffffu, m == vit);
        if (lane == __ffs(bal) - 1) {
            g_best = ibase + idx;
            if (out_size > SEQ) out[SEQ] = vit;   // path score
        }
    }

    // No CTA may exit while peers' DSMEM stores targeting it are in flight
    asm volatile("barrier.cluster.arrive.aligned;" ::: "memory");
    asm volatile("barrier.cluster.wait.aligned;"   ::: "memory");
}

// ---------------------------------------------------------------------------
// Backpointer recompute: bp[t][j] = argmax_i(hist[t][i] + tr[j][i]).
// Fully parallel over (j-group, t-chunk); warp = one tag, lane = 16 sources.
// ---------------------------------------------------------------------------
__device__ __forceinline__ void bp_step(const float (&a)[16], const float (&tr)[16],
                                        int t, int j, int ibase, int lane) {
    float s[16];
    s[0] = a[0] + tr[0];
    float m = s[0];
#pragma unroll
    for (int k = 1; k < 16; ++k) { s[k] = a[k] + tr[k]; m = fmaxf(m, s[k]); }
    const float vit = dec32(__reduce_max_sync(0xffffffffu, enc32(m)));
    int idx = 0;
#pragma unroll
    for (int k = 15; k >= 0; --k) if (s[k] == vit) idx = k;       // first index
    const unsigned bal = __ballot_sync(0xffffffffu, m == vit);
    if (lane == __ffs(bal) - 1)
        g_bp[t][j] = (unsigned short)(ibase + idx);
}

__global__ void __launch_bounds__(BP_JGRP * 32, 4)
viterbi_bp(const float* __restrict__ trans) {
    const int warp  = threadIdx.x >> 5;
    const int lane  = threadIdx.x & 31;
    const int j     = blockIdx.x * BP_JGRP + warp;
    const int ibase = lane << 4;
    const int t0    = blockIdx.y * BP_TCH;

    float tr[16];
#pragma unroll
    for (int q = 0; q < 4; ++q) {
        float4 v = __ldg((const float4*)(trans + j * NT + ibase) + q);
        tr[4*q]=v.x; tr[4*q+1]=v.y; tr[4*q+2]=v.z; tr[4*q+3]=v.w;
    }

    float a[16], b[16];
#pragma unroll
    for (int q = 0; q < 4; ++q) {
        float4 v = __ldg((const float4*)(&g_hist[t0][ibase]) + q);
        a[4*q]=v.x; a[4*q+1]=v.y; a[4*q+2]=v.z; a[4*q+3]=v.w;
    }

#pragma unroll 1
    for (int tt = 0; tt < BP_TCH; tt += 2) {
        const int t = t0 + tt;
#pragma unroll
        for (int q = 0; q < 4; ++q) {                 // prefetch t+1
            float4 v = __ldg((const float4*)(&g_hist[t + 1][ibase]) + q);
            b[4*q]=v.x; b[4*q+1]=v.y; b[4*q+2]=v.z; b[4*q+3]=v.w;
        }
        bp_step(a, tr, t, j, ibase, lane);
#pragma unroll
        for (int q = 0; q < 4; ++q) {                 // prefetch t+2 (row exists: <= SEQ)
            float4 v = __ldg((const float4*)(&g_hist[t + 2][ibase]) + q);
            a[4*q]=v.x; a[4*q+1]=v.y; a[4*q+2]=v.z; a[4*q+3]=v.w;
        }
        bp_step(b, tr, t + 1, j, ibase, lane);
    }
}

// ---------------------------------------------------------------------------
// Traceback pass A: per-segment exit map for every possible entry tag.
// ---------------------------------------------------------------------------
__global__ void viterbi_exits() {
    const int s = blockIdx.x;
    int cur = threadIdx.x;
    const int tbase = s * SEGLEN;
    for (int t = tbase + SEGLEN - 1; t >= tbase; --t)
        cur = g_bp[t][cur];
    g_exit[s][threadIdx.x] = (unsigned short)cur;
}

// ---------------------------------------------------------------------------
// Traceback pass B (sequential compose) + C (parallel path write)
// ---------------------------------------------------------------------------
__global__ void viterbi_trace(float* __restrict__ out, int out_size) {
    __shared__ int entry[SEGS];
    const int tid = threadIdx.x;
    if (tid == 0) {
        int cur = g_best;
        for (int s = SEGS - 1; s >= 0; --s) {
            entry[s] = cur;
            cur = g_exit[s][cur];
        }
    }
    __syncthreads();
    int cur = entry[tid];
    const int tbase = tid * SEGLEN;
    for (int t = tbase + SEGLEN - 1; t >= tbase; --t) {
        if (t < out_size) out[t] = (float)cur;
        cur = g_bp[t][cur];
    }
}

// ---------------------------------------------------------------------------
// Launch
// ---------------------------------------------------------------------------
extern "C" void kernel_launch(void* const* d_in, const int* in_sizes, int n_in,
                              void* d_out, int out_size) {
    const float* unary = (const float*)d_in[0];   // [SEQ,1,NT] f32
    const float* trans = (const float*)d_in[1];   // [1,NT,NT]  f32
    (void)in_sizes; (void)n_in;                   // lengths == SEQ, unused
    float* out = (float*)d_out;

    viterbi_fwd  <<<CLN, FW_TPB>>>(unary, trans, out, out_size);
    viterbi_bp   <<<dim3(BP_GRIDX, BP_GRIDY), BP_JGRP * 32>>>(trans);
    viterbi_exits<<<SEGS, NT>>>();
    viterbi_trace<<<1, SEGS>>>(out, out_size);
}